// round 3
// baseline (speedup 1.0000x reference)
#include <cuda_runtime.h>
#include <math.h>

#define NB    8
#define NCC   16384
#define HIDD  128
#define OUTD  64
#define LDA_H 132
#define LDA_O 68
#define WLD   136

#define OFF_T1  8448
#define OFF_O   16896
#define OFF_WT  21248
#define OFF_TEN 25600
#define OFF_AUX 25664
#define SMEM_FLOATS 25696
#define SMEM_BYTES  (SMEM_FLOATS * 4)

// ---------------- device scratch (no allocation allowed) ----------------
__device__ float g_ea1b[NB * 128];
__device__ float g_eg1b[NB * 128];
__device__ float g_aabs[NB];
__device__ float g_fsum[NB * 8 * HIDD];
__device__ float g_dsum[NB * 8 * HIDD];
__device__ float g_fm[NB * 8 * HIDD];
__device__ float g_m0[NB * HIDD];
__device__ float g_interf[HIDD];
__device__ float g_numer[OUTD];
__device__ float g_denom, g_tsum;

// ---------------- Stage A: per-branch folded biases + zeroing ----------------
__global__ void __launch_bounds__(256) stageA(
    const float* __restrict__ x, const float* __restrict__ noise,
    const float* __restrict__ amps,
    const float* __restrict__ eaW1, const float* __restrict__ eaB1,
    const float* __restrict__ egW1, const float* __restrict__ egB1)
{
    __shared__ float sXB[NB * 64];
    int tid = threadIdx.x;
    for (int i = tid; i < NB * 8 * HIDD; i += 256) { g_fsum[i] = 0.f; g_dsum[i] = 0.f; }
    if (tid < OUTD) g_numer[tid] = 0.f;
    if (tid == 0) {
        g_denom = 0.f; g_tsum = 0.f;
        float s = 1e-8f, t[NB];
        for (int b = 0; b < NB; b++) { t[b] = fabsf(amps[b]); s += t[b]; }
        for (int b = 0; b < NB; b++) g_aabs[b] = t[b] / s;
    }
    for (int i = tid; i < NB * 64; i += 256) {
        int b = i >> 6, k = i & 63;
        sXB[i] = x[k] + noise[i] * 0.05f * (float)(b + 1);
    }
    __syncthreads();
    for (int i = tid; i < NB * 128; i += 256) {
        int b = i >> 7, j = i & 127;
        float s1 = eaB1[j], s2 = egB1[j];
        const float* xb = sXB + b * 64;
        #pragma unroll 8
        for (int k = 0; k < 64; k++) {
            s1 = fmaf(xb[k], eaW1[j * 192 + k], s1);
            s2 = fmaf(xb[k], egW1[j * 192 + k], s2);
        }
        g_ea1b[i] = s1; g_eg1b[i] = s2;
    }
}

// ---------------- GEMM tile helper ----------------
#define FMA16(a4, w0, w1, w2, w3, i) \
  acc[i][0]=fmaf(a4.x,w0.x,acc[i][0]); acc[i][1]=fmaf(a4.x,w0.y,acc[i][1]); \
  acc[i][2]=fmaf(a4.x,w0.z,acc[i][2]); acc[i][3]=fmaf(a4.x,w0.w,acc[i][3]); \
  acc[i][0]=fmaf(a4.y,w1.x,acc[i][0]); acc[i][1]=fmaf(a4.y,w1.y,acc[i][1]); \
  acc[i][2]=fmaf(a4.y,w1.z,acc[i][2]); acc[i][3]=fmaf(a4.y,w1.w,acc[i][3]); \
  acc[i][0]=fmaf(a4.z,w2.x,acc[i][0]); acc[i][1]=fmaf(a4.z,w2.y,acc[i][1]); \
  acc[i][2]=fmaf(a4.z,w2.z,acc[i][2]); acc[i][3]=fmaf(a4.z,w2.w,acc[i][3]); \
  acc[i][0]=fmaf(a4.w,w3.x,acc[i][0]); acc[i][1]=fmaf(a4.w,w3.y,acc[i][1]); \
  acc[i][2]=fmaf(a4.w,w3.z,acc[i][2]); acc[i][3]=fmaf(a4.w,w3.w,acc[i][3]);

__device__ __forceinline__ void gemm_tile(
    float (&acc)[8][4], const float* __restrict__ sA, int lda,
    const float* __restrict__ W, int ldw, int row0, int colOff,
    int K, int N, float* sWT, int tid, int r0, int cg)
{
    for (int kt = 0; kt < K; kt += 32) {
        __syncthreads();
        for (int idx = tid; idx < N * 32; idx += 256) {
            int j = idx >> 5, kk = idx & 31;
            sWT[kk * WLD + j] = W[(row0 + j) * ldw + colOff + kt + kk];
        }
        __syncthreads();
        if (cg * 4 < N) {
            #pragma unroll 2
            for (int kk = 0; kk < 32; kk += 4) {
                float4 w0 = *(const float4*)(sWT + (kk + 0) * WLD + cg * 4);
                float4 w1 = *(const float4*)(sWT + (kk + 1) * WLD + cg * 4);
                float4 w2 = *(const float4*)(sWT + (kk + 2) * WLD + cg * 4);
                float4 w3 = *(const float4*)(sWT + (kk + 3) * WLD + cg * 4);
                #pragma unroll
                for (int i = 0; i < 8; i++) {
                    float4 a = *(const float4*)(sA + (r0 + i) * lda + kt + kk);
                    FMA16(a, w0, w1, w2, w3, i)
                }
            }
        }
    }
}

// ---------------- Stage B: fused per-cell pipeline ----------------
__global__ void __launch_bounds__(256, 1) stageB(
    const float* __restrict__ hiddens,
    const float* __restrict__ eaW1, const float* __restrict__ eaW2, const float* __restrict__ eaB2,
    const float* __restrict__ egW1, const float* __restrict__ egW2, const float* __restrict__ egB2,
    const float* __restrict__ Wih,  const float* __restrict__ Whh,
    const float* __restrict__ bih,  const float* __restrict__ bhh,
    float* __restrict__ out, long long nh_off)
{
    extern __shared__ float sm[];
    float* sH   = sm;
    float* sT1  = sm + OFF_T1;
    float* sO   = sm + OFF_O;
    float* sWT  = sm + OFF_WT;
    float* sTen = sm + OFF_TEN;
    float* sAux = sm + OFF_AUX;

    const int tid = threadIdx.x;
    const int rg = tid >> 5, cg = tid & 31, r0 = rg * 8;
    const int c0 = blockIdx.x * 8;
    const int b = rg;

    if (tid < 8) sAux[16 + tid] = g_aabs[tid];
    for (int idx = tid; idx < 64 * 128; idx += 256) {
        int r = idx >> 7, k = idx & 127;
        sH[r * LDA_H + k] = hiddens[((long long)((r >> 3) * NCC + c0 + (r & 7))) * HIDD + k];
    }

    float acc[8][4];

    // t1a = relu(biasA + H @ eaW1h^T)
    #pragma unroll
    for (int j = 0; j < 4; j++) {
        float bj = g_ea1b[b * 128 + cg * 4 + j];
        #pragma unroll
        for (int i = 0; i < 8; i++) acc[i][j] = bj;
    }
    gemm_tile(acc, sH, LDA_H, eaW1, 192, 0, 64, 128, 128, sWT, tid, r0, cg);
    #pragma unroll
    for (int i = 0; i < 8; i++)
        *(float4*)(sT1 + (r0 + i) * LDA_H + cg * 4) =
            make_float4(fmaxf(acc[i][0], 0.f), fmaxf(acc[i][1], 0.f),
                        fmaxf(acc[i][2], 0.f), fmaxf(acc[i][3], 0.f));

    // a = t1a @ eaW2^T + eaB2
    #pragma unroll
    for (int j = 0; j < 4; j++) {
        float bj = (cg < 16) ? eaB2[cg * 4 + j] : 0.f;
        #pragma unroll
        for (int i = 0; i < 8; i++) acc[i][j] = bj;
    }
    gemm_tile(acc, sT1, LDA_H, eaW2, 128, 0, 0, 128, 64, sWT, tid, r0, cg);
    if (cg < 16) {
        #pragma unroll
        for (int i = 0; i < 8; i++)
            *(float4*)(sO + (r0 + i) * LDA_O + cg * 4) =
                make_float4(acc[i][0], acc[i][1], acc[i][2], acc[i][3]);
    }

    // t1g
    #pragma unroll
    for (int j = 0; j < 4; j++) {
        float bj = g_eg1b[b * 128 + cg * 4 + j];
        #pragma unroll
        for (int i = 0; i < 8; i++) acc[i][j] = bj;
    }
    gemm_tile(acc, sH, LDA_H, egW1, 192, 0, 64, 128, 128, sWT, tid, r0, cg);
    #pragma unroll
    for (int i = 0; i < 8; i++)
        *(float4*)(sT1 + (r0 + i) * LDA_H + cg * 4) =
            make_float4(fmaxf(acc[i][0], 0.f), fmaxf(acc[i][1], 0.f),
                        fmaxf(acc[i][2], 0.f), fmaxf(acc[i][3], 0.f));

    // g ; out = a - g
    #pragma unroll
    for (int j = 0; j < 4; j++) {
        float bj = (cg < 16) ? egB2[cg * 4 + j] : 0.f;
        #pragma unroll
        for (int i = 0; i < 8; i++) acc[i][j] = bj;
    }
    gemm_tile(acc, sT1, LDA_H, egW2, 128, 0, 0, 128, 64, sWT, tid, r0, cg);
    if (cg < 16) {
        #pragma unroll
        for (int i = 0; i < 8; i++) {
            float4* p = (float4*)(sO + (r0 + i) * LDA_O + cg * 4);
            float4 v = *p;
            v.x -= acc[i][0]; v.y -= acc[i][1]; v.z -= acc[i][2]; v.w -= acc[i][3];
            *p = v;
        }
    }
    __syncthreads();

    // tension
    if (tid < 64) {
        float s = 0.f;
        #pragma unroll 16
        for (int o = 0; o < 64; o++) { float v = sO[tid * LDA_O + o]; s = fmaf(v, v, s); }
        sTen[tid] = s * (1.f / 64.f);
    }
    __syncthreads();
    if (tid < 8) {
        float s = 0.f;
        #pragma unroll
        for (int bb = 0; bb < 8; bb++) s += sTen[bb * 8 + tid];
        float avg = s * 0.125f;
        sAux[tid] = avg; sAux[8 + tid] = expf(avg);
    }
    __syncthreads();
    if (tid < 64) {
        float v = 0.f;
        for (int ci = 0; ci < 8; ci++) {
            float co = 0.f;
            #pragma unroll
            for (int bb = 0; bb < 8; bb++)
                co = fmaf(sAux[16 + bb], sO[(bb * 8 + ci) * LDA_O + tid], co);
            v = fmaf(sAux[8 + ci], co, v);
        }
        atomicAdd(&g_numer[tid], v);
    } else if (tid == 64) {
        float se = 0.f, st = 0.f;
        for (int ci = 0; ci < 8; ci++) { se += sAux[8 + ci]; st += sAux[ci]; }
        atomicAdd(&g_denom, se); atomicAdd(&g_tsum, st);
    }

    // ---- GRU ----
    // r gate -> parked in sT1 (thread-exclusive slots, reduces register pressure)
    #pragma unroll
    for (int j = 0; j < 4; j++) {
        int u = cg * 4 + j;
        float base = bih[u] + bhh[u];
        float wt = Wih[u * 65 + 64];
        #pragma unroll
        for (int i = 0; i < 8; i++) acc[i][j] = fmaf(sTen[r0 + i], wt, base);
    }
    gemm_tile(acc, sO, LDA_O, Wih, 65, 0, 0, 64, 128, sWT, tid, r0, cg);
    gemm_tile(acc, sH, LDA_H, Whh, 128, 0, 0, 128, 128, sWT, tid, r0, cg);
    #pragma unroll
    for (int i = 0; i < 8; i++)
        #pragma unroll
        for (int j = 0; j < 4; j++)
            sT1[(r0 + i) * LDA_H + cg * 4 + j] = 1.f / (1.f + expf(-acc[i][j]));

    // z gate (registers)
    float zReg[8][4];
    #pragma unroll
    for (int j = 0; j < 4; j++) {
        int u = 128 + cg * 4 + j;
        float base = bih[u] + bhh[u];
        float wt = Wih[u * 65 + 64];
        #pragma unroll
        for (int i = 0; i < 8; i++) acc[i][j] = fmaf(sTen[r0 + i], wt, base);
    }
    gemm_tile(acc, sO, LDA_O, Wih, 65, 128, 0, 64, 128, sWT, tid, r0, cg);
    gemm_tile(acc, sH, LDA_H, Whh, 128, 128, 0, 128, 128, sWT, tid, r0, cg);
    #pragma unroll
    for (int i = 0; i < 8; i++)
        #pragma unroll
        for (int j = 0; j < 4; j++) zReg[i][j] = 1.f / (1.f + expf(-acc[i][j]));

    // n gate: inn (acc) and hn (accH) kept separate
    float accH[8][4];
    #pragma unroll
    for (int j = 0; j < 4; j++) {
        int u = 256 + cg * 4 + j;
        float bi = bih[u], bh = bhh[u];
        float wt = Wih[u * 65 + 64];
        #pragma unroll
        for (int i = 0; i < 8; i++) { acc[i][j] = fmaf(sTen[r0 + i], wt, bi); accH[i][j] = bh; }
    }
    gemm_tile(acc,  sO, LDA_O, Wih, 65, 256, 0, 64, 128, sWT, tid, r0, cg);
    gemm_tile(accH, sH, LDA_H, Whh, 128, 256, 0, 128, 128, sWT, tid, r0, cg);

    // combine -> newh v0 into sT1, faction sums via atomics
    const int f = c0 >> 11;
    const bool deb = (c0 & 2047) < 512;
    float fs[4] = {0.f, 0.f, 0.f, 0.f};
    #pragma unroll
    for (int i = 0; i < 8; i++) {
        int r = r0 + i;
        float4 hv = *(const float4*)(sH + r * LDA_H + cg * 4);
        float h[4] = {hv.x, hv.y, hv.z, hv.w};
        #pragma unroll
        for (int j = 0; j < 4; j++) {
            float rr = sT1[r * LDA_H + cg * 4 + j];
            float n = tanhf(acc[i][j] + rr * accH[i][j]);
            float zz = zReg[i][j];
            float v = (1.f - zz) * n + zz * h[j];
            sT1[r * LDA_H + cg * 4 + j] = v;
            fs[j] += v;
        }
    }
    #pragma unroll
    for (int j = 0; j < 4; j++) {
        int u = cg * 4 + j;
        atomicAdd(&g_fsum[(b * 8 + f) * HIDD + u], fs[j]);
        if (deb) atomicAdd(&g_dsum[(b * 8 + f) * HIDD + u], fs[j]);
    }
    __syncthreads();

    // coalesced copy-out of v0
    for (int idx = tid; idx < 64 * 128; idx += 256) {
        int r = idx >> 7, k = idx & 127;
        out[nh_off + ((long long)((r >> 3) * NCC + c0 + (r & 7))) * HIDD + k] = sT1[r * LDA_H + k];
    }
}

// ---------------- Stage C: means, interf, pred, scalar ----------------
__global__ void __launch_bounds__(256) stageC(
    const float* __restrict__ mixW, const float* __restrict__ mixb,
    const float* __restrict__ headW, const float* __restrict__ headb,
    const int* __restrict__ stepp, float* __restrict__ out, long long nh_off)
{
    __shared__ float sMF[NB * HIDD];
    __shared__ float sC[OUTD];
    int tid = threadIdx.x;
    int st = *stepp;
    for (int i = tid; i < NB * HIDD; i += 256) {
        int b = i >> 7, u = i & 127;
        float Sf = 0.f, Sd = 0.f;
        for (int f = 0; f < 8; f++) {
            float fsv = g_fsum[(b * 8 + f) * HIDD + u];
            float fm  = fsv * (1.f / 2048.f);
            g_fm[(b * 8 + f) * HIDD + u] = fm;
            Sf += fsv;
            Sd += 0.85f * g_dsum[(b * 8 + f) * HIDD + u] + 76.8f * fm;
        }
        float m0 = Sf * (1.f / 16384.f);
        g_m0[i] = m0;
        sMF[i] = (st > 5) ? (m0 + 0.15f * (0.25f * m0 - Sd * (1.f / 16384.f))) : m0;
    }
    __syncthreads();
    if (tid < HIDD) {
        float v = mixb[tid];
        #pragma unroll 16
        for (int t = 0; t < NB * HIDD; t++) v = fmaf(sMF[t], mixW[tid * (NB * HIDD) + t], v);
        g_interf[tid] = v;
    }
    if (tid >= 128 && tid < 192) sC[tid - 128] = g_numer[tid - 128] / g_denom;
    __syncthreads();
    if (tid < OUTD) {
        float p = headb[tid];
        #pragma unroll
        for (int o = 0; o < OUTD; o++) p = fmaf(sC[o], headW[tid * OUTD + o], p);
        out[tid] = p;
    } else if (tid == 64) {
        out[nh_off - 1] = g_tsum * (1.f / 16384.f);
    }
}

// ---------------- Stage D: elementwise sync/debate/interf ----------------
__global__ void __launch_bounds__(256) stageD(const int* __restrict__ stepp,
                                              float* __restrict__ out, long long nh_off)
{
    long long idx = (long long)blockIdx.x * 256 + threadIdx.x;
    int u = (int)(idx & 127);
    long long rc = idx >> 7;
    int c = (int)(rc & (NCC - 1));
    int b = (int)(rc >> 14);
    float v0 = out[nh_off + idx];
    int f = c >> 11;
    float v = 0.85f * v0 + 0.15f * g_fm[(b * 8 + f) * HIDD + u];
    if (*stepp > 5 && (c & 2047) < 512) v = 0.85f * v + 0.15f * g_m0[b * HIDD + u];
    if (b == 0) v += 0.05f * g_interf[u];
    out[nh_off + idx] = v;
}

extern "C" void kernel_launch(void* const* d_in, const int* in_sizes, int n_in,
                              void* d_out, int out_size) {
    const float* x     = (const float*)d_in[0];
    const float* noise = (const float*)d_in[1];
    const float* amps  = (const float*)d_in[2];
    const float* hidd  = (const float*)d_in[3];
    const float* eaW1  = (const float*)d_in[4];
    const float* eaB1  = (const float*)d_in[5];
    const float* eaW2  = (const float*)d_in[6];
    const float* eaB2  = (const float*)d_in[7];
    const float* egW1  = (const float*)d_in[8];
    const float* egB1  = (const float*)d_in[9];
    const float* egW2  = (const float*)d_in[10];
    const float* egB2  = (const float*)d_in[11];
    const float* Wih   = (const float*)d_in[12];
    const float* Whh   = (const float*)d_in[13];
    const float* bih   = (const float*)d_in[14];
    const float* bhh   = (const float*)d_in[15];
    const float* headW = (const float*)d_in[16];
    const float* headb = (const float*)d_in[17];
    const float* mixW  = (const float*)d_in[18];
    const float* mixb  = (const float*)d_in[19];
    const int*   step  = (const int*)d_in[20];
    float* out = (float*)d_out;
    long long nh_off = (long long)out_size - (long long)NB * NCC * HIDD;

    cudaFuncSetAttribute(stageB, cudaFuncAttributeMaxDynamicSharedMemorySize, SMEM_BYTES);

    stageA<<<1, 256>>>(x, noise, amps, eaW1, eaB1, egW1, egB1);
    stageB<<<NCC / 8, 256, SMEM_BYTES>>>(hidd, eaW1, eaW2, eaB2, egW1, egW2, egB2,
                                         Wih, Whh, bih, bhh, out, nh_off);
    stageC<<<1, 256>>>(mixW, mixb, headW, headb, step, out, nh_off);
    stageD<<<(NB * NCC * HIDD) / 256, 256>>>(step, out, nh_off);
}